// round 3
// baseline (speedup 1.0000x reference)
#include <cuda_runtime.h>
#include <cstdint>

#define T_TOK 4096
#define E_DIM 1024
#define DFF   4096
#define BB    4
#define NSTEP 128
#define TPAD  (T_TOK + 32)
#define GRID  128
#define NTHR  512

// ---------------- device global scratch ----------------
__device__ float    g_M[64 * 64];                       // w_fft2 @ w_fft1
__device__ float    g_LNx[(size_t)BB * TPAD * E_DIM];   // LN1(x) for all token slots (+pad)
__device__ float    g_cnlo[BB * 32 * E_DIM];            // LN1(prev proc rows 32..63)
__device__ uint32_t g_cn2t[BB * 64 * E_DIM];            // LN2 output, tf32 bits
__device__ uint32_t g_ft[(size_t)BB * 64 * DFF];        // sin(gate)*val, tf32 bits
__device__ float    g_part[4 * BB * 64 * E_DIM];        // split-K partials
__device__ uint32_t g_wupt[(size_t)2 * DFF * E_DIM];    // w_up tf32
__device__ uint32_t g_wdnt[(size_t)E_DIM * DFF];        // w_down tf32
__device__ unsigned g_bar;                              // grid barrier counter

// ---------------- helpers ----------------
__device__ __forceinline__ uint32_t f2tf(float f) {
    uint32_t r;
    asm("cvt.rna.tf32.f32 %0, %1;" : "=r"(r) : "f"(f));
    return r;
}
__device__ __forceinline__ void mma8(float4& d, const uint32_t* a, const uint32_t* b) {
    asm volatile(
        "mma.sync.aligned.m16n8k8.row.col.f32.tf32.tf32.f32 "
        "{%0,%1,%2,%3},{%4,%5,%6,%7},{%8,%9},{%0,%1,%2,%3};\n"
        : "+f"(d.x), "+f"(d.y), "+f"(d.z), "+f"(d.w)
        : "r"(a[0]), "r"(a[1]), "r"(a[2]), "r"(a[3]), "r"(b[0]), "r"(b[1]));
}
__device__ __forceinline__ uint32_t smem_u32(const void* p) {
    return (uint32_t)__cvta_generic_to_shared(p);
}
__device__ __forceinline__ float4 ldcg4(const float* p) {
    float4 v;
    asm volatile("ld.global.cg.v4.f32 {%0,%1,%2,%3},[%4];"
                 : "=f"(v.x), "=f"(v.y), "=f"(v.z), "=f"(v.w) : "l"(p));
    return v;
}
__device__ __forceinline__ float2 ldcg2(const float* p) {
    float2 v;
    asm volatile("ld.global.cg.v2.f32 {%0,%1},[%2];" : "=f"(v.x), "=f"(v.y) : "l"(p));
    return v;
}
#define CP16(dst, src) asm volatile("cp.async.cg.shared.global [%0],[%1],16;\n" :: "r"(dst), "l"(src))
#define CPCOMMIT()     asm volatile("cp.async.commit_group;\n")
#define CPWAIT1()      asm volatile("cp.async.wait_group 1;\n")
#define CPWAIT0()      asm volatile("cp.async.wait_group 0;\n")

// monotonic-counter grid barrier (all 128 blocks resident by construction)
__device__ __forceinline__ void gsync(unsigned& cnt) {
    __threadfence();
    __syncthreads();
    if (threadIdx.x == 0) {
        cnt += GRID;
        atomicAdd(&g_bar, 1u);
        while (atomicAdd(&g_bar, 0u) < cnt) {}
        __threadfence();
    }
    __syncthreads();
}

// ---------------- init kernels ----------------
__global__ void initM_kernel(const float* __restrict__ wfft1, const float* __restrict__ wfft2) {
    int idx = blockIdx.x * 256 + threadIdx.x;  // 4096
    if (idx == 0) g_bar = 0;                   // reset barrier each launch
    int t = idx >> 6, s = idx & 63;
    float acc = 0.f;
#pragma unroll
    for (int u = 0; u < 48; u++)
        acc += wfft2[t * 48 + u] * wfft1[u * 64 + s];
    g_M[t * 64 + s] = acc;
}

__global__ void cvt_all_kernel(const float* __restrict__ wup, const float* __restrict__ wdn) {
    size_t i = ((size_t)blockIdx.x * 256 + threadIdx.x) * 4;
    const size_t NUP = (size_t)2 * DFF * E_DIM;  // 8388608
    if (i < NUP) {
        float4 v = *(const float4*)(wup + i);
        *(uint4*)(g_wupt + i) = make_uint4(f2tf(v.x), f2tf(v.y), f2tf(v.z), f2tf(v.w));
    } else {
        size_t j = i - NUP;
        float4 v = *(const float4*)(wdn + j);
        *(uint4*)(g_wdnt + j) = make_uint4(f2tf(v.x), f2tf(v.y), f2tf(v.z), f2tf(v.w));
    }
}

__global__ void lnx_kernel(const float* __restrict__ x,
                           const float* __restrict__ w, const float* __restrict__ bias) {
    int row = blockIdx.x;              // 0 .. BB*TPAD-1
    int b = row / TPAD, j = row % TPAD;
    int tid = threadIdx.x;

    float4 v = make_float4(0.f, 0.f, 0.f, 0.f);
    if (j < T_TOK) v = *(const float4*)(x + ((size_t)b * T_TOK + j) * E_DIM + tid * 4);

    float s = v.x + v.y + v.z + v.w;
    float q = v.x * v.x + v.y * v.y + v.z * v.z + v.w * v.w;
#pragma unroll
    for (int o = 16; o > 0; o >>= 1) {
        s += __shfl_xor_sync(0xffffffffu, s, o);
        q += __shfl_xor_sync(0xffffffffu, q, o);
    }
    __shared__ float sh[2][8];
    int wi = tid >> 5, l = tid & 31;
    if (l == 0) { sh[0][wi] = s; sh[1][wi] = q; }
    __syncthreads();
    if (wi == 0) {
        s = (l < 8) ? sh[0][l] : 0.f;
        q = (l < 8) ? sh[1][l] : 0.f;
#pragma unroll
        for (int o = 4; o > 0; o >>= 1) {
            s += __shfl_xor_sync(0xffffffffu, s, o);
            q += __shfl_xor_sync(0xffffffffu, q, o);
        }
        if (l == 0) { sh[0][0] = s; sh[1][0] = q; }
    }
    __syncthreads();
    s = sh[0][0]; q = sh[1][0];
    float mu = s * (1.f / E_DIM);
    float var = q * (1.f / E_DIM) - mu * mu;
    float inv = rsqrtf(var + 1e-5f);
    float4 wv = ((const float4*)w)[tid];
    float4 bv = ((const float4*)bias)[tid];
    float4 o;
    o.x = (v.x - mu) * inv * wv.x + bv.x;
    o.y = (v.y - mu) * inv * wv.y + bv.y;
    o.z = (v.z - mu) * inv * wv.z + bv.z;
    o.w = (v.w - mu) * inv * wv.w + bv.w;
    *(float4*)(g_LNx + ((size_t)b * TPAD + j) * E_DIM + tid * 4) = o;
    if (j < 32)
        *(float4*)(g_cnlo + ((size_t)b * 32 + j) * E_DIM + tid * 4) = o;
}

// ---------------- persistent scan kernel ----------------
// Phases per step: A fft+LN2 (64 blocks x 4 rows) | B up GEMM (128 tiles)
//                  C down GEMM splitK4 (128 tiles) | D reduce+LN1 (64 blocks x 4 rows)
__global__ __launch_bounds__(NTHR, 1) void scan_kernel(
    const float* __restrict__ x,
    const float* __restrict__ ln1w, const float* __restrict__ ln1b,
    const float* __restrict__ ln2w, const float* __restrict__ ln2b,
    const float* __restrict__ bup,  const float* __restrict__ bdn,
    float* __restrict__ dout)
{
    extern __shared__ uint32_t sm[];           // 65536 B: sCN (A) / pipeline (B,C)
    __shared__ float sMrow[4][64];
    __shared__ float sRed[2][16];

    const int tid = threadIdx.x, bid = blockIdx.x;
    const int warp = tid >> 5, lane = tid & 31, grp = lane >> 2, tig = lane & 3;
    const int wm = warp >> 2, wn = warp & 3;
    unsigned bcnt = 0;

    // phase A/D mapping (valid when bid < 64)
    const int arr = tid >> 7;          // row-in-block 0..3
    const int aj  = tid & 127;         // 0..127 -> 2 e's per (et)
    const int arow0 = bid * 4;
    const int arow = arow0 + arr;
    const int ab = arow >> 6, at = arow & 63;

    // phase B mapping
    const int ubx = bid & 63, uby = bid >> 6;
    // phase C mapping
    const int dbx = bid & 15, dby = (bid >> 4) & 1, dbz = bid >> 5;

    float2 r2v[4];   // res2 slice held across phases

    for (int step = 0; step < NSTEP; step++) {
        //================ Phase A: fft + LN2 ================
        if (bid < 64) {
            if (tid < 256)
                sMrow[tid >> 6][tid & 63] = g_M[((arow0 & 63) + (tid >> 6)) * 64 + (tid & 63)];
            float psum = 0.f, psq = 0.f;
            float* sCN = (float*)sm;                 // [64][256]
            for (int et = 0; et < 4; et++) {
                __syncthreads();
#pragma unroll
                for (int q = 0; q < 8; q++) {
                    int idx = q * 512 + tid;
                    int s = idx >> 6, c4 = (idx & 63) * 4;
                    float4 v;
                    if (s < 32)
                        v = ldcg4(g_cnlo + ((size_t)(ab * 32 + s)) * E_DIM + et * 256 + c4);
                    else
                        v = *(const float4*)(g_LNx + ((size_t)ab * TPAD + step * 32 + s) * E_DIM + et * 256 + c4);
                    *(float4*)(sCN + s * 256 + c4) = v;
                }
                __syncthreads();
                float a0 = 0.f, a1 = 0.f;
                const float*  mr  = sMrow[arr];
                const float2* cp2 = (const float2*)sCN + aj;   // row stride 128 float2
#pragma unroll 16
                for (int s = 0; s < 64; s++) {
                    float m = mr[s];
                    float2 c = cp2[s * 128];
                    a0 += m * c.x;
                    a1 += m * c.y;
                }
                int e = et * 256 + aj * 2;
                int gt = step * 32 + at;
                if (gt < T_TOK) {
                    float2 xv = *(const float2*)(x + ((size_t)ab * T_TOK + gt) * E_DIM + e);
                    a0 += xv.x; a1 += xv.y;
                }
                r2v[et] = make_float2(a0, a1);
                psum += a0 + a1;
                psq  += a0 * a0 + a1 * a1;
            }
            // LN2: reduce across the 4 warps of this row
#pragma unroll
            for (int o = 16; o > 0; o >>= 1) {
                psum += __shfl_xor_sync(0xffffffffu, psum, o);
                psq  += __shfl_xor_sync(0xffffffffu, psq, o);
            }
            if (lane == 0) { sRed[0][warp] = psum; sRed[1][warp] = psq; }
            __syncthreads();
            float s4 = 0.f, q4 = 0.f;
#pragma unroll
            for (int w = 0; w < 4; w++) { s4 += sRed[0][arr * 4 + w]; q4 += sRed[1][arr * 4 + w]; }
            float mu = s4 * (1.f / E_DIM);
            float var = q4 * (1.f / E_DIM) - mu * mu;
            float inv = rsqrtf(var + 1e-5f);
#pragma unroll
            for (int et = 0; et < 4; et++) {
                int e = et * 256 + aj * 2;
                float2 wv = *(const float2*)(ln2w + e);
                float2 bv = *(const float2*)(ln2b + e);
                uint2 o;
                o.x = f2tf((r2v[et].x - mu) * inv * wv.x + bv.x);
                o.y = f2tf((r2v[et].y - mu) * inv * wv.y + bv.y);
                *(uint2*)(g_cn2t + (size_t)arow * E_DIM + e) = o;
            }
        }
        gsync(bcnt);

        //================ Phase B: up GEMM + sin gating ================
        {
            const int r = tid >> 2, c0 = (tid & 3) * 4;
            const uint32_t* gA = g_cn2t + (size_t)(uby * 128 + r) * E_DIM + c0;
            int wn_ = r >> 5, rr_ = r & 31;
            int wrow = (rr_ < 16) ? (ubx * 64 + wn_ * 16 + rr_)
                                  : (DFF + ubx * 64 + wn_ * 16 + (rr_ - 16));
            const uint32_t* gB = g_wupt + (size_t)wrow * E_DIM + c0;
            const uint32_t sb = smem_u32(sm);
            const uint32_t dA = sb + (r * 20 + c0) * 4;
            const uint32_t dB = sb + (2560 + r * 20 + c0) * 4;
            const uint32_t slotB = 5120 * 4;

            float4 acc[2][4];
#pragma unroll
            for (int i = 0; i < 2; i++)
#pragma unroll
                for (int j = 0; j < 4; j++) acc[i][j] = make_float4(0.f, 0.f, 0.f, 0.f);

            CP16(dA, gA); CP16(dB, gB); CPCOMMIT();
            CP16(dA + slotB, gA + 16); CP16(dB + slotB, gB + 16); CPCOMMIT();

            for (int k = 0; k < 64; k++) {
                if (k < 63) CPWAIT1(); else CPWAIT0();
                __syncthreads();
                if (k + 2 < 64) {
                    uint32_t so = ((k + 2) % 3) * slotB;
                    int off = (k + 2) * 16;
                    CP16(dA + so, gA + off); CP16(dB + so, gB + off); CPCOMMIT();
                }
                const uint32_t* As = sm + (k % 3) * 5120;
                const uint32_t* Bs = As + 2560;
#pragma unroll
                for (int kk = 0; kk < 16; kk += 8) {
                    uint32_t af[2][4], bf[4][2];
#pragma unroll
                    for (int tm = 0; tm < 2; tm++) {
                        int ra = wm * 32 + tm * 16 + grp;
                        af[tm][0] = As[ra * 20 + kk + tig];
                        af[tm][1] = As[(ra + 8) * 20 + kk + tig];
                        af[tm][2] = As[ra * 20 + kk + tig + 4];
                        af[tm][3] = As[(ra + 8) * 20 + kk + tig + 4];
                    }
#pragma unroll
                    for (int tn = 0; tn < 4; tn++) {
                        int rb = wn * 32 + tn * 8 + grp;
                        bf[tn][0] = Bs[rb * 20 + kk + tig];
                        bf[tn][1] = Bs[rb * 20 + kk + tig + 4];
                    }
#pragma unroll
                    for (int tm = 0; tm < 2; tm++)
#pragma unroll
                        for (int tn = 0; tn < 4; tn++)
                            mma8(acc[tm][tn], af[tm], bf[tn]);
                }
            }
            // epilogue: gate tn pairs with val tn+2
#pragma unroll
            for (int tm = 0; tm < 2; tm++) {
#pragma unroll
                for (int tn = 0; tn < 2; tn++) {
                    float4 g = acc[tm][tn];
                    float4 v = acc[tm][tn + 2];
                    int jg = ubx * 64 + wn * 16 + tn * 8 + 2 * tig;
                    float bg0 = bup[jg], bg1 = bup[jg + 1];
                    float bv0 = bup[DFF + jg], bv1 = bup[DFF + jg + 1];
                    int m0 = uby * 128 + wm * 32 + tm * 16 + grp;
                    uint2 lo, hi;
                    lo.x = f2tf(__sinf(g.x + bg0) * (v.x + bv0));
                    lo.y = f2tf(__sinf(g.y + bg1) * (v.y + bv1));
                    hi.x = f2tf(__sinf(g.z + bg0) * (v.z + bv0));
                    hi.y = f2tf(__sinf(g.w + bg1) * (v.w + bv1));
                    *(uint2*)(g_ft + (size_t)m0 * DFF + jg) = lo;
                    *(uint2*)(g_ft + (size_t)(m0 + 8) * DFF + jg) = hi;
                }
            }
        }
        gsync(bcnt);

        //================ Phase C: down GEMM (split-K=4) ================
        {
            const int r = tid >> 2, c0 = (tid & 3) * 4;
            const uint32_t* gA = g_ft + (size_t)(dby * 128 + r) * DFF + dbz * 1024 + c0;
            const bool ldB = tid < 256;
            const uint32_t* gB = g_wdnt + (size_t)(dbx * 64 + r) * DFF + dbz * 1024 + c0;
            const uint32_t sb = smem_u32(sm);
            const uint32_t dA = sb + (r * 20 + c0) * 4;
            const uint32_t dB = sb + (2560 + r * 20 + c0) * 4;   // r<64 when ldB
            const uint32_t slotB = 3840 * 4;

            float4 acc[2][2];
#pragma unroll
            for (int i = 0; i < 2; i++) {
                acc[i][0] = make_float4(0.f, 0.f, 0.f, 0.f);
                acc[i][1] = make_float4(0.f, 0.f, 0.f, 0.f);
            }

            CP16(dA, gA); if (ldB) CP16(dB, gB); CPCOMMIT();
            CP16(dA + slotB, gA + 16); if (ldB) CP16(dB + slotB, gB + 16); CPCOMMIT();

            for (int k = 0; k < 64; k++) {
                if (k < 63) CPWAIT1(); else CPWAIT0();
                __syncthreads();
                if (k + 2 < 64) {
                    uint32_t so = ((k + 2) % 3) * slotB;
                    int off = (k + 2) * 16;
                    CP16(dA + so, gA + off); if (ldB) CP16(dB + so, gB + off); CPCOMMIT();
                }
                const uint32_t* As = sm + (k % 3) * 3840;
                const uint32_t* Bs = As + 2560;
#pragma unroll
                for (int kk = 0; kk < 16; kk += 8) {
                    uint32_t af[2][4], bf[2][2];
#pragma unroll
                    for (int tm = 0; tm < 2; tm++) {
                        int ra = wm * 32 + tm * 16 + grp;
                        af[tm][0] = As[ra * 20 + kk + tig];
                        af[tm][1] = As[(ra + 8) * 20 + kk + tig];
                        af[tm][2] = As[ra * 20 + kk + tig + 4];
                        af[tm][3] = As[(ra + 8) * 20 + kk + tig + 4];
                    }
#pragma unroll
                    for (int tn = 0; tn < 2; tn++) {
                        int rb = wn * 16 + tn * 8 + grp;
                        bf[tn][0] = Bs[rb * 20 + kk + tig];
                        bf[tn][1] = Bs[rb * 20 + kk + tig + 4];
                    }
#pragma unroll
                    for (int tm = 0; tm < 2; tm++)
#pragma unroll
                        for (int tn = 0; tn < 2; tn++)
                            mma8(acc[tm][tn], af[tm], bf[tn]);
                }
            }
#pragma unroll
            for (int tm = 0; tm < 2; tm++) {
#pragma unroll
                for (int tn = 0; tn < 2; tn++) {
                    int n = dbx * 64 + wn * 16 + tn * 8 + 2 * tig;
                    int m = dby * 128 + wm * 32 + tm * 16 + grp;
                    float4 a = acc[tm][tn];
                    *(float2*)(g_part + (size_t)(dbz * 256 + m) * E_DIM + n) = make_float2(a.x, a.y);
                    *(float2*)(g_part + (size_t)(dbz * 256 + m + 8) * E_DIM + n) = make_float2(a.z, a.w);
                }
            }
        }
        gsync(bcnt);

        //================ Phase D: reduce + LN1(carry) ================
        if (bid < 64) {
            float psum = 0.f, psq = 0.f;
            float2 vv[4];
#pragma unroll
            for (int et = 0; et < 4; et++) {
                int e = et * 256 + aj * 2;
                size_t off = (size_t)arow * E_DIM + e;
                float2 p0 = ldcg2(g_part + off);
                float2 p1 = ldcg2(g_part + 262144 + off);
                float2 p2 = ldcg2(g_part + 524288 + off);
                float2 p3 = ldcg2(g_part + 786432 + off);
                float2 bd = *(const float2*)(bdn + e);
                float2 v;
                v.x = p0.x + p1.x + p2.x + p3.x + bd.x + r2v[et].x;
                v.y = p0.y + p1.y + p2.y + p3.y + bd.y + r2v[et].y;
                vv[et] = v;
                psum += v.x + v.y;
                psq  += v.x * v.x + v.y * v.y;
            }
#pragma unroll
            for (int o = 16; o > 0; o >>= 1) {
                psum += __shfl_xor_sync(0xffffffffu, psum, o);
                psq  += __shfl_xor_sync(0xffffffffu, psq, o);
            }
            if (lane == 0) { sRed[0][warp] = psum; sRed[1][warp] = psq; }
            __syncthreads();
            if (at < 32) {
#pragma unroll
                for (int et = 0; et < 4; et++) {
                    int e = et * 256 + aj * 2;
                    *(float2*)(dout + ((size_t)ab * T_TOK + step * 32 + at) * E_DIM + e) = vv[et];
                }
            } else {
                float s4 = 0.f, q4 = 0.f;
#pragma unroll
                for (int w = 0; w < 4; w++) { s4 += sRed[0][arr * 4 + w]; q4 += sRed[1][arr * 4 + w]; }
                float mu = s4 * (1.f / E_DIM);
                float var = q4 * (1.f / E_DIM) - mu * mu;
                float inv = rsqrtf(var + 1e-5f);
#pragma unroll
                for (int et = 0; et < 4; et++) {
                    int e = et * 256 + aj * 2;
                    float2 wv = *(const float2*)(ln1w + e);
                    float2 bv = *(const float2*)(ln1b + e);
                    float2 o;
                    o.x = (vv[et].x - mu) * inv * wv.x + bv.x;
                    o.y = (vv[et].y - mu) * inv * wv.y + bv.y;
                    *(float2*)(g_cnlo + ((size_t)(ab * 32 + (at - 32))) * E_DIM + e) = o;
                }
            }
        }
        gsync(bcnt);
    }
}

// ---------------- launch ----------------
extern "C" void kernel_launch(void* const* d_in, const int* in_sizes, int n_in,
                              void* d_out, int out_size) {
    const float* x     = (const float*)d_in[0];
    const float* ln1w  = (const float*)d_in[1];
    const float* ln1b  = (const float*)d_in[2];
    const float* wfft1 = (const float*)d_in[3];
    const float* wfft2 = (const float*)d_in[4];
    const float* ln2w  = (const float*)d_in[5];
    const float* ln2b  = (const float*)d_in[6];
    const float* wup   = (const float*)d_in[7];
    const float* bup   = (const float*)d_in[8];
    const float* wdn   = (const float*)d_in[9];
    const float* bdn   = (const float*)d_in[10];
    float* out = (float*)d_out;

    cudaFuncSetAttribute(scan_kernel, cudaFuncAttributeMaxDynamicSharedMemorySize, 65536);

    initM_kernel<<<16, 256>>>(wfft1, wfft2);                 // also resets g_bar
    cvt_all_kernel<<<12288, 256>>>(wup, wdn);
    lnx_kernel<<<BB * TPAD, 256>>>(x, ln1w, ln1b);
    scan_kernel<<<GRID, NTHR, 65536>>>(x, ln1w, ln1b, ln2w, ln2b, bup, bdn, out);
}